// round 15
// baseline (speedup 1.0000x reference)
#include <cuda_runtime.h>
#include <cstdint>
#include <math.h>

// Problem constants
#define NB 32     // batch
#define NP 192    // patches
#define NA 30     // attributes
#define NE 256    // embed dim
#define NK 768    // input feature dim
#define SV 193    // visual seq len
#define ST 31     // textual seq len

#define VE_OFF 0
#define TE_OFF 8192
#define PM_OFF 16384
#define AM_OFF 24576
#define SIM_OFF 32768

// Scratch
__device__ float g_patch[NB * NP * NE];    // [v][p][e]
__device__ float g_patchT[NB * NE * NP];   // [v][e][p]
__device__ float g_att[NB * NA * NE];      // [t][a][e]
__device__ float g_attT[NE * NB * NA];     // [e][row]
__device__ float g_rp[NB * NP];
__device__ float g_ra[NB * NA];
__device__ float g_G[NB * NA * 32];
__device__ float g_WT[4 * NK * NE];        // transposed weights [seg][k][n]
__device__ float g_M[NB * NB * NA * NP];   // [v][t*30+a][p]

typedef unsigned long long ull;

__device__ __forceinline__ void fma2(ull& d, ull a, ull b) {
    asm("fma.rn.f32x2 %0, %1, %2, %3;" : "=l"(d) : "l"(a), "l"(b), "l"(d));
}
__device__ __forceinline__ ull pk2(float x, float y) {
    ull r; asm("mov.b64 %0, {%1,%2};" : "=l"(r) : "f"(x), "f"(y)); return r;
}
__device__ __forceinline__ float2 upk(ull v) {
    float2 r; asm("mov.b64 {%0,%1}, %2;" : "=f"(r.x), "=f"(r.y) : "l"(v)); return r;
}
__device__ __forceinline__ void cpa16(uint32_t s, const void* g) {
    asm volatile("cp.async.cg.shared.global [%0], [%1], 16;\n" :: "r"(s), "l"(g));
}
__device__ __forceinline__ void cpa_commit() {
    asm volatile("cp.async.commit_group;\n" ::: "memory");
}
template<int N>
__device__ __forceinline__ void cpa_wait() {
    asm volatile("cp.async.wait_group %0;\n" :: "n"(N) : "memory");
}

// ---------------------------------------------------------------------------
// Transpose the four weight matrices [256][768] -> g_WT[seg][768][256]
// ---------------------------------------------------------------------------
__global__ __launch_bounds__(256) void wt_kernel(
    const float* __restrict__ W0, const float* __restrict__ W1,
    const float* __restrict__ W2, const float* __restrict__ W3)
{
    __shared__ float ts[32][33];
    const int z = blockIdx.z;
    const float* W = (z == 0) ? W0 : (z == 1) ? W1 : (z == 2) ? W2 : W3;
    const int k0 = blockIdx.x * 32;
    const int n0 = blockIdx.y * 32;
    const int lane = threadIdx.x & 31, wid = threadIdx.x >> 5;
#pragma unroll
    for (int i = 0; i < 4; i++)
        ts[wid + 8 * i][lane] = W[(size_t)(n0 + wid + 8 * i) * NK + k0 + lane];
    __syncthreads();
    float* WT = g_WT + (size_t)z * NK * NE;
#pragma unroll
    for (int i = 0; i < 4; i++)
        WT[(size_t)(k0 + wid + 8 * i) * NE + n0 + lane] = ts[lane][wid + 8 * i];
}

// ---------------------------------------------------------------------------
// Merged projection GEMM, cp.async triple-buffered.
// seg 0 (patch) additionally writes g_patchT; seg 1 (att) writes g_attT.
// ---------------------------------------------------------------------------
#define PA_SZ (64 * 36)
#define PB_SZ (32 * 64)
__global__ __launch_bounds__(256) void proj2_kernel(
    const float* __restrict__ vf, const float* __restrict__ tf,
    const float* __restrict__ b_patch, const float* __restrict__ b_att,
    const float* __restrict__ b_vis, const float* __restrict__ b_txt,
    float* __restrict__ out)
{
    extern __shared__ float psm[];

    const int y = blockIdx.y;
    int seg, my;
    if (y < 96)       { seg = 0; my = y; }
    else if (y < 111) { seg = 1; my = y - 96; }
    else if (y == 111){ seg = 2; my = 0; }
    else              { seg = 3; my = 0; }

    const int M  = (seg == 0) ? NB * NP : (seg == 1) ? NB * NA : NB;
    const int S  = (seg == 0 || seg == 2) ? SV : ST;
    const int gs = (seg == 0) ? NP : (seg == 1) ? NA : 1;
    const int off= (seg <= 1) ? 1 : 0;
    const float* X = (seg == 0 || seg == 2) ? vf : tf;
    const float* bias = (seg == 0) ? b_patch : (seg == 1) ? b_att
                       : (seg == 2) ? b_vis : b_txt;
    float* obase;
    if (seg == 0) obase = g_patch;
    else if (seg == 1) obase = g_att;
    else if (seg == 2) obase = out + VE_OFF;
    else obase = out + TE_OFF;
    const float* WT = g_WT + (size_t)seg * NK * NE;

    const int col0 = blockIdx.x * 64;
    const int row0 = my * 64;
    const int tid = threadIdx.x;
    const int tm = tid >> 4, tn = tid & 15;

    const int c1 = tid + 256;
    const int ar0 = tid >> 3,  ac0 = (tid & 7) << 2;
    const int ar1 = c1 >> 3,   ac1 = (c1 & 7) << 2;
    int gr0 = row0 + ar0; if (gr0 >= M) gr0 = M - 1;
    int gr1 = row0 + ar1; if (gr1 >= M) gr1 = M - 1;
    const float* aS0 = X + (size_t)((gr0 / gs) * S + off + gr0 % gs) * NK + ac0;
    const float* aS1 = X + (size_t)((gr1 / gs) * S + off + gr1 % gs) * NK + ac1;
    const uint32_t aD0 = (ar0 * 36 + ac0) * 4;
    const uint32_t aD1 = (ar1 * 36 + ac1) * 4;
    const int bk0 = tid >> 4, bc0 = (tid & 15) << 2;
    const int bk1 = c1 >> 4,  bc1 = (c1 & 15) << 2;
    const float* bS0 = WT + (size_t)bk0 * NE + col0 + bc0;
    const float* bS1 = WT + (size_t)bk1 * NE + col0 + bc1;
    const uint32_t bD0 = (bk0 * 64 + bc0) * 4;
    const uint32_t bD1 = (bk1 * 64 + bc1) * 4;

    const uint32_t sA = (uint32_t)__cvta_generic_to_shared(psm);
    const uint32_t sB = (uint32_t)__cvta_generic_to_shared(psm + 3 * PA_SZ);

    ull c2[4][2];
#pragma unroll
    for (int i = 0; i < 4; i++) { c2[i][0] = 0ull; c2[i][1] = 0ull; }

#pragma unroll
    for (int pb = 0; pb < 2; pb++) {
        const uint32_t oA = sA + pb * (PA_SZ * 4);
        const uint32_t oB = sB + pb * (PB_SZ * 4);
        const int k0 = pb * 32;
        cpa16(oA + aD0, aS0 + k0);
        cpa16(oA + aD1, aS1 + k0);
        cpa16(oB + bD0, bS0 + (size_t)k0 * NE);
        cpa16(oB + bD1, bS1 + (size_t)k0 * NE);
        cpa_commit();
    }

    for (int it = 0; it < 24; it++) {
        if (it < 22) {
            const int nb = (it + 2) % 3;
            const uint32_t oA = sA + nb * (PA_SZ * 4);
            const uint32_t oB = sB + nb * (PB_SZ * 4);
            const int k0 = (it + 2) * 32;
            cpa16(oA + aD0, aS0 + k0);
            cpa16(oA + aD1, aS1 + k0);
            cpa16(oB + bD0, bS0 + (size_t)k0 * NE);
            cpa16(oB + bD1, bS1 + (size_t)k0 * NE);
            cpa_commit();
            cpa_wait<2>();
        } else if (it == 22) {
            cpa_wait<1>();
        } else {
            cpa_wait<0>();
        }
        __syncthreads();

        const float* A = psm + (it % 3) * PA_SZ;
        const float* B = psm + 3 * PA_SZ + (it % 3) * PB_SZ;
#pragma unroll
        for (int q = 0; q < 8; q++) {
            float4 a[4];
#pragma unroll
            for (int i = 0; i < 4; i++)
                a[i] = *(const float4*)&A[(tm * 4 + i) * 36 + q * 4];
#pragma unroll
            for (int j = 0; j < 4; j++) {
                ulonglong2 bb = *(const ulonglong2*)&B[(q * 4 + j) * 64 + tn * 4];
#pragma unroll
                for (int i = 0; i < 4; i++) {
                    float av = (j == 0) ? a[i].x : (j == 1) ? a[i].y
                             : (j == 2) ? a[i].z : a[i].w;
                    ull d = pk2(av, av);
                    fma2(c2[i][0], d, bb.x);
                    fma2(c2[i][1], d, bb.y);
                }
            }
        }
        __syncthreads();
    }

    const float4 b4 = *(const float4*)&bias[col0 + tn * 4];
    float* Cs = psm;   // 64 x 69 staging (buffers dead)
#pragma unroll
    for (int i = 0; i < 4; i++) {
        int r = row0 + tm * 4 + i;
        float2 lo = upk(c2[i][0]), hi = upk(c2[i][1]);
        float4 o;
        o.x = lo.x + b4.x; o.y = lo.y + b4.y;
        o.z = hi.x + b4.z; o.w = hi.y + b4.w;
        if (r < M)
            *(float4*)&obase[(size_t)r * NE + col0 + tn * 4] = o;
        if (seg <= 1) {
            float* cr = &Cs[(tm * 4 + i) * 69 + tn * 4];
            cr[0] = o.x; cr[1] = o.y; cr[2] = o.z; cr[3] = o.w;
        }
    }

    if (seg == 0) {
        __syncthreads();
        const int v = row0 / NP, p0 = row0 % NP;
        float* dT = g_patchT + (size_t)v * NE * NP;
#pragma unroll
        for (int i = 0; i < 16; i++) {
            int idx = tid + 256 * i;
            int e = idx >> 6, p = idx & 63;
            dT[(size_t)(col0 + e) * NP + p0 + p] = Cs[p * 69 + e];
        }
    } else if (seg == 1) {
        __syncthreads();
#pragma unroll
        for (int i = 0; i < 16; i++) {
            int idx = tid + 256 * i;
            int e = idx >> 6, p = idx & 63;
            g_attT[(size_t)(col0 + e) * (NB * NA) + row0 + p] = Cs[p * 69 + e];
        }
    }
}

// ---------------------------------------------------------------------------
// Fused M GEMM + prep (unchanged from R14).
// ---------------------------------------------------------------------------
#define MA_SZ (32 * 196)
#define MB_SZ (32 * 100)
#define MBUF  (MA_SZ + MB_SZ)
__global__ __launch_bounds__(256, 2) void mgemm_prep_kernel(
    const int* __restrict__ att_nums, float* __restrict__ out)
{
    extern __shared__ float psm[];
    const int r = blockIdx.x;
    const int tid = threadIdx.x;
    const int lane = tid & 31, wid = tid >> 5;

    if (r < 320) {
        const int nt = r & 1;
        const int mt = (r >> 1) % 5;
        const int v  = r / 10;
        const float* Bg = g_patchT + (size_t)v * NE * NP;
        float* C = g_M + (size_t)v * (NB * NA) * NP;

        const int tm = tid >> 4, tn = tid & 15;
        const uint32_t sbase = (uint32_t)__cvta_generic_to_shared(psm);

        ull c2[12][3];
#pragma unroll
        for (int i = 0; i < 12; i++)
#pragma unroll
            for (int j = 0; j < 3; j++) c2[i][j] = 0ull;

        int crow[9], coff[9];
        bool isA[9];
#pragma unroll
        for (int j = 0; j < 9; j++) {
            int c = tid + 256 * j;
            if (c < 1536) { isA[j] = true;  crow[j] = c / 48; coff[j] = (c % 48) * 4; }
            else { int b = c - 1536; isA[j] = false; crow[j] = b / 24; coff[j] = (b % 24) * 4; }
        }

#pragma unroll
        for (int j = 0; j < 9; j++) {
            if (isA[j])
                cpa16(sbase + (uint32_t)(crow[j] * 196 + coff[j]) * 4,
                      g_attT + (size_t)crow[j] * (NB * NA) + mt * 192 + coff[j]);
            else
                cpa16(sbase + (uint32_t)(MA_SZ + crow[j] * 100 + coff[j]) * 4,
                      Bg + (size_t)crow[j] * NP + nt * 96 + coff[j]);
        }
        cpa_commit();

        for (int it = 0; it < 8; it++) {
            if (it < 7) {
                const int nb = (it + 1) & 1;
                const int k0 = (it + 1) * 32;
                const uint32_t bb = sbase + (uint32_t)(nb * MBUF) * 4;
#pragma unroll
                for (int j = 0; j < 9; j++) {
                    if (isA[j])
                        cpa16(bb + (uint32_t)(crow[j] * 196 + coff[j]) * 4,
                              g_attT + (size_t)(k0 + crow[j]) * (NB * NA) + mt * 192 + coff[j]);
                    else
                        cpa16(bb + (uint32_t)(MA_SZ + crow[j] * 100 + coff[j]) * 4,
                              Bg + (size_t)(k0 + crow[j]) * NP + nt * 96 + coff[j]);
                }
                cpa_commit();
                cpa_wait<1>();
            } else {
                cpa_wait<0>();
            }
            __syncthreads();

            const float* As = psm + (it & 1) * MBUF;
            const float* Bs = As + MA_SZ;
#pragma unroll
            for (int k = 0; k < 32; k++) {
                const float* ap = &As[k * 196 + tm * 12];
                float4 a0 = *(const float4*)&ap[0];
                float4 a1 = *(const float4*)&ap[4];
                float4 a2 = *(const float4*)&ap[8];
                const float* bp = &Bs[k * 100 + tn * 6];
                ull b0 = *(const ull*)&bp[0];
                ull b1 = *(const ull*)&bp[2];
                ull b2 = *(const ull*)&bp[4];
                float av[12] = {a0.x, a0.y, a0.z, a0.w, a1.x, a1.y, a1.z, a1.w,
                                a2.x, a2.y, a2.z, a2.w};
#pragma unroll
                for (int i = 0; i < 12; i++) {
                    ull d = pk2(av[i], av[i]);
                    fma2(c2[i][0], d, b0);
                    fma2(c2[i][1], d, b1);
                    fma2(c2[i][2], d, b2);
                }
            }
            __syncthreads();
        }

#pragma unroll
        for (int i = 0; i < 12; i++) {
            float* cr = &C[(size_t)(mt * 192 + tm * 12 + i) * NP + nt * 96 + tn * 6];
#pragma unroll
            for (int j = 0; j < 3; j++) {
                float2 f = upk(c2[i][j]);
                *(float2*)&cr[2 * j] = f;
            }
        }
    } else if (r < 1208) {
        const int w = (r - 320) * 8 + wid;
        if (w >= NB * NP + NB * NA) return;
        const float* row;
        float* dst;
        if (w < NB * NP) { row = g_patch + (size_t)w * NE; dst = &g_rp[w]; }
        else { row = g_att + (size_t)(w - NB * NP) * NE; dst = &g_ra[w - NB * NP]; }
        float4 x0 = *(const float4*)&row[lane * 4];
        float4 x1 = *(const float4*)&row[128 + lane * 4];
        float ss = x0.x * x0.x + x0.y * x0.y + x0.z * x0.z + x0.w * x0.w
                 + x1.x * x1.x + x1.y * x1.y + x1.z * x1.z + x1.w * x1.w;
#pragma unroll
        for (int o = 16; o > 0; o >>= 1) ss += __shfl_xor_sync(~0u, ss, o);
        if (lane == 0) *dst = rsqrtf(fmaxf(ss, 1e-24f));
    } else if (r < 1240) {
        const int t = r - 1208;
        const float* ap = g_att + (size_t)t * NA * NE;
        for (int i = tid; i < NA * NE; i += 256) psm[i] = ap[i];
        __syncthreads();
        for (int idx = tid; idx < NA * NA; idx += 256) {
            int a = idx / NA, b = idx % NA;
            const float* ra = psm + a * NE;
            const float* rb = psm + b * NE;
            float acc = 0.f;
#pragma unroll 4
            for (int e = 0; e < NE; e += 4) {
                float4 x = *(float4*)&ra[e];
                float4 y = *(float4*)&rb[e];
                acc += x.x * y.x + x.y * y.y + x.z * y.z + x.w * y.w;
            }
            g_G[t * NA * 32 + a * 32 + b] = acc;
        }
    } else {
        const int b = r - 1240;
        const int e = tid;
        float pm = 0.f;
        const float* pb = g_patch + (size_t)b * NP * NE + e;
#pragma unroll 4
        for (int p = 0; p < NP; p++) pm += pb[(size_t)p * NE];
        out[PM_OFF + b * NE + e] = pm / (float)NP;
        float am = 0.f;
        const float* ab = g_att + (size_t)b * NA * NE + e;
#pragma unroll
        for (int a = 0; a < NA; a++) am += ab[(size_t)a * NE];
        out[AM_OFF + b * NE + e] = am / (float)att_nums[b];
    }
}

// ---------------------------------------------------------------------------
// Pair kernel smem layout (floats). Total 27009 fl = 108036 B -> 2 CTAs/SM.
// attn1 stored DUPLICATED: s_A1d[a][2p] = s_A1d[a][2p+1] = attn1[a][p], so
// stage C loads packed (w,w) pairs with one LDS.64 broadcast (no pk2 movs).
// ---------------------------------------------------------------------------
#define SB_M    0          /* 5760  : M [30][192] */
#define SB_A1D  5760       /* 11520 : attn1 dup [30][384] */
#define SB_RG   17280      /* 8192  : A2 (5760) / tiles 2x4096 / comb 7680 */
#define SB_G    25472      /* 960 */
#define SB_RA   26432      /* 32 */
#define SB_RP   26464      /* 192 */
#define SB_PADF 26656      /* 32 */
#define SB_W    26688      /* 192 */
#define SB_W2   26880      /* 32 */
#define SB_C    26912      /* 32 */
#define SB_RED  26944      /* 64 */
#define SB_AN   27008      /* 1 */
#define SMEM_F  27009

__global__ __launch_bounds__(384, 2) void pair_kernel(const int* __restrict__ mask,
                                                      const int* __restrict__ att_nums,
                                                      float* __restrict__ out_sim)
{
    extern __shared__ float sm[];
    const int v = blockIdx.x, t = blockIdx.y;
    const int tid = threadIdx.x, lane = tid & 31, wid = tid >> 5;

    float* s_M    = sm + SB_M;
    float* s_A1d  = sm + SB_A1D;
    float* s_rg   = sm + SB_RG;
    float* s_A2   = sm + SB_RG;      // alias phase 1
    float* s_G    = sm + SB_G;
    float* s_ra   = sm + SB_RA;
    float* s_rp   = sm + SB_RP;
    float* s_padf = sm + SB_PADF;
    float* s_w    = sm + SB_W;
    float* s_w2   = sm + SB_W2;
    float* s_c    = sm + SB_C;
    float* s_red  = sm + SB_RED;
    float* s_an   = sm + SB_AN;

    // ---- preload (vectorized) ----
    const float* Mg = g_M + ((size_t)v * (NB * NA) + t * NA) * NP;
    for (int i = tid; i < NA * NP / 4; i += 384)
        *(float4*)&s_M[i * 4] = *(const float4*)&Mg[i * 4];
    const float* gGp = g_G + t * NA * 32;
    for (int i = tid; i < NA * 8; i += 384)
        *(float4*)&s_G[i * 4] = *(const float4*)&gGp[i * 4];
    if (tid < NA) {
        s_ra[tid] = g_ra[t * NA + tid];
        s_padf[tid] = (mask[t * NA + tid] != 0) ? 1.f : 0.f;
    }
    if (tid < NP) s_rp[tid] = g_rp[v * NP + tid];
    if (tid == 0) s_an[0] = (float)att_nums[t];
    __syncthreads();

    const float* pbase = g_patch + (size_t)v * NP * NE;

    // ---- attn1: softmax over p, written duplicated (warp per row) ----
    for (int r = wid; r < NA; r += 12) {
        const float ra = s_ra[r];
        float x[6];
        float mx = 0.f;
#pragma unroll
        for (int j = 0; j < 6; j++) {
            int p = lane + j * 32;
            float d = fmaxf(s_M[r * NP + p] * ra * s_rp[p], 0.f) * 20.f;
            x[j] = d; mx = fmaxf(mx, d);
        }
#pragma unroll
        for (int o = 16; o > 0; o >>= 1) mx = fmaxf(mx, __shfl_xor_sync(~0u, mx, o));
        float ssum = 0.f;
#pragma unroll
        for (int j = 0; j < 6; j++) { x[j] = __expf(x[j] - mx); ssum += x[j]; }
#pragma unroll
        for (int o = 16; o > 0; o >>= 1) ssum += __shfl_xor_sync(~0u, ssum, o);
        const float rinv = 1.f / ssum;
#pragma unroll
        for (int j = 0; j < 6; j++) {
            float val = x[j] * rinv;
            int p = lane + j * 32;
            float2 d2; d2.x = val; d2.y = val;
            *(float2*)&s_A1d[r * 384 + 2 * p] = d2;
        }
    }

    // ---- attn2: 2 threads per p (lane-adjacent), 15 a's each.
    //      masked softmax + f32x2 Gram quadratic -> w_p; A2 stored ----
    {
        const int p = tid >> 1;
        const int sub = tid & 1;
        const int abase = sub * 15;
        const float rp = s_rp[p];
        float vv[15];
        float mx = -1.f;
#pragma unroll
        for (int j = 0; j < 15; j++) {
            const int a = abase + j;
            float d = fmaxf(s_M[a * NP + p] * s_ra[a] * rp, 0.f) * 20.f;
            if (s_padf[a] == 0.f) { vv[j] = d; mx = fmaxf(mx, d); }
            else                  { vv[j] = -1.f; }
        }
        mx = fmaxf(mx, __shfl_xor_sync(~0u, mx, 1));
        float ssum = 0.f;
#pragma unroll
        for (int j = 0; j < 15; j++) {
            float e = (vv[j] < 0.f) ? 0.f : __expf(vv[j] - mx);
            vv[j] = e; ssum += e;
        }
        ssum += __shfl_xor_sync(~0u, ssum, 1);
        const float rinv = 1.f / ssum;
#pragma unroll
        for (int j = 0; j < 15; j++) { vv[j] *= rinv; s_A2[(abase + j) * NP + p] = vv[j]; }
        // partner's normalized values
        float ov[15];
#pragma unroll
        for (int j = 0; j < 15; j++) ov[j] = __shfl_xor_sync(~0u, vv[j], 1);
        // y_b for own b's: sub0 -> pairs b=0..13 + scalar b=14
        //                  sub1 -> scalar b=15 + pairs b=16..29 (8B-aligned pairs)
        const int pb0 = sub ? 16 : 0;     // first paired b
        const int sb  = sub ? 15 : 14;    // scalar b
        ull y2[7];
#pragma unroll
        for (int k = 0; k < 7; k++) y2[k] = 0ull;
        float ysc = 0.f;
#pragma unroll
        for (int a = 0; a < NA; a++) {
            float va = (a < 15) ? (sub ? ov[a] : vv[a])
                                : (sub ? vv[a - 15] : ov[a - 15]);
            ull vd = pk2(va, va);
            const float* Gr = s_G + a * 32;
#pragma unroll
            for (int k = 0; k < 7; k++)
                fma2(y2[k], vd, *(const ull*)&Gr[pb0 + 2 * k]);
            ysc = fmaf(va, Gr[sb], ysc);
        }
        float z = 0.f;
        const int vj0 = sub ? 1 : 0;     // vv index of first paired b
#pragma unroll
        for (int k = 0; k < 7; k++) {
            float2 yk = upk(y2[k]);
            z = fmaf(vv[vj0 + 2 * k], yk.x, z);
            z = fmaf(vv[vj0 + 2 * k + 1], yk.y, z);
        }
        z = fmaf(vv[sub ? 0 : 14], ysc, z);
        z += __shfl_xor_sync(~0u, z, 1);
        if (sub == 0) s_w[p] = rsqrtf(fmaxf(z, 1e-24f));
    }
    __syncthreads();

    // ---- c_a = sum_p attn2[a][p] * w_p (warp per row) ----
    for (int r = wid; r < NA; r += 12) {
        float cc = 0.f;
#pragma unroll
        for (int j = 0; j < 6; j++) {
            int p = lane + j * 32;
            cc = fmaf(s_A2[r * NP + p], s_w[p], cc);
        }
#pragma unroll
        for (int o = 16; o > 0; o >>= 1) cc += __shfl_xor_sync(~0u, cc, o);
        if (lane == 0) s_c[r] = cc;
    }
    __syncthreads();   // c done; region free for tiles

    // ---- Stage C: ||attend_patch_a||^2.
    // 384 threads: h = p-half, 6 a-groups x 5 a's, 32 e-threads.
    // Weights loaded as packed (w,w) LDS.64 broadcasts from s_A1d.
    {
        const int h  = (tid >= 192) ? 1 : 0;
        const int g  = tid - h * 192;     // 0..191
        const int a0 = (g >> 5) * 5;      // 0,5,...,25
        const int e4 = (g & 31) * 4;
        float* tA = s_rg;
        float* tB = s_rg + 4096;

        ull acc[5][4];
#pragma unroll
        for (int a = 0; a < 5; a++)
#pragma unroll
            for (int k = 0; k < 4; k++) acc[a][k] = 0ull;

#pragma unroll
        for (int i = 0; i < 3; i++) {
            int fid = tid + 384 * i;
            if (fid < 1024) {
                int row = fid >> 6, col = (fid & 63) << 2;
                *(float4*)&tA[row * NE + col] =
                    *(const float4*)&pbase[(size_t)row * NE + col];
            }
        }
        __syncthreads();

        for (int pt = 0; pt < 12; pt++) {
            float4 lv[3];
            if (pt < 11) {
#pragma unroll
                for (int i = 0; i < 3; i++) {
                    int fid = tid + 384 * i;
                    if (fid < 1024) {
                        int row = fid >> 6, col = (fid & 63) << 2;
                        lv[i] = *(const float4*)&pbase[(size_t)((pt + 1) * 16 + row) * NE + col];
                    }
                }
            }
            const float* tl = (pt & 1) ? tB : tA;
            const int p0l = h * 8;
            const int p0g = pt * 16 + p0l;
#pragma unroll
            for (int pp = 0; pp < 8; pp += 2) {
                ulonglong2 uLo0 = *(const ulonglong2*)&tl[(p0l + pp) * NE + e4];
                ulonglong2 uHi0 = *(const ulonglong2*)&tl[(p0l + pp) * NE + 128 + e4];
                ulonglong2 uLo1 = *(const ulonglong2*)&tl[(p0l + pp + 1) * NE + e4];
                ulonglong2 uHi1 = *(const ulonglong2*)&tl[(p0l + pp + 1) * NE + 128 + e4];
#pragma unroll
                for (int a = 0; a < 5; a++) {
                    const float* dup = &s_A1d[(a0 + a) * 384 + 2 * (p0g + pp)];
                    ull w0 = *(const ull*)&dup[0];     // (w_p, w_p) broadcast
                    ull w1 = *(const ull*)&dup[2];     // (w_{p+1}, w_{p+1})
                    fma2(acc[a][0], w0, uLo0.x); fma2(acc[a][1], w0, uLo0.y);
                    fma2(acc[a][2], w0, uHi0.x); fma2(acc[a][3], w0, uHi0.y);
                    fma2(acc[a][0], w1, uLo1.x); fma2(acc[a][1], w1, uLo1.y);
                    fma2(acc[a][2], w1, uHi1.x); fma2(acc[a][3], w1, uHi1.y);
                }
            }
            if (pt < 11) {
                float* tn_ = (pt & 1) ? tA : tB;
#pragma unroll
                for (int i = 0; i < 3; i++) {
                    int fid = tid + 384 * i;
                    if (fid < 1024) {
                        int row = fid >> 6, col = (fid & 63) << 2;
                        *(float4*)&tn_[row * NE + col] = lv[i];
                    }
                }
            }
            __syncthreads();
        }

        // combine halves (vector add BEFORE squaring): one pass, 5 a's
        float* s_comb = s_rg;    // 192 * 40 = 7680 <= 8192
        if (h == 1) {
#pragma unroll
            for (int a = 0; a < 5; a++)
#pragma unroll
                for (int k = 0; k < 4; k++) {
                    float2 f = upk(acc[a][k]);
                    *(float2*)&s_comb[g * 40 + a * 8 + k * 2] = f;
                }
        }
        __syncthreads();
        if (h == 0) {
#pragma unroll
            for (int a = 0; a < 5; a++) {
                float ss = 0.f;
#pragma unroll
                for (int k = 0; k < 4; k++) {
                    float2 fc = *(const float2*)&s_comb[g * 40 + a * 8 + k * 2];
                    float2 f = upk(acc[a][k]);
                    float sx = f.x + fc.x, sy = f.y + fc.y;
                    ss += sx * sx + sy * sy;
                }
#pragma unroll
                for (int o = 16; o > 0; o >>= 1)
                    ss += __shfl_xor_sync(~0u, ss, o);
                if (lane == 0) s_red[a0 + a] = ss;
            }
        }
        __syncthreads();
    }
    if (tid < NA)
        s_w2[tid] = (s_padf[tid] != 0.f) ? 0.f : rsqrtf(fmaxf(s_red[tid], 1e-24f));
    __syncthreads();

    // ---- final: sim = sum_p d_p * (sum_a c_a M[a][p]) / (an*30) ----
    float fp = 0.f;
    if (tid < NP) {
        const int p = tid;
        float dp = 0.f, mp = 0.f;
#pragma unroll
        for (int a = 0; a < NA; a++) {
            dp = fmaf(s_A1d[a * 384 + 2 * p], s_w2[a], dp);
            mp = fmaf(s_c[a], s_M[a * NP + p], mp);
        }
        fp = dp * mp;
    }
#pragma unroll
    for (int o = 16; o > 0; o >>= 1) fp += __shfl_xor_sync(~0u, fp, o);
    if (lane == 0) s_red[32 + wid] = fp;
    __syncthreads();
    if (tid == 0) {
        float tot = 0.f;
#pragma unroll
        for (int w2i = 0; w2i < 12; w2i++) tot += s_red[32 + w2i];
        out_sim[t * NB + v] = tot / (s_an[0] * (float)NA);
    }
}

// ---------------------------------------------------------------------------
extern "C" void kernel_launch(void* const* d_in, const int* in_sizes, int n_in,
                              void* d_out, int out_size)
{
    const float* vf      = (const float*)d_in[0];
    const float* tf      = (const float*)d_in[1];
    const int*   mask    = (const int*)d_in[2];
    const int*   att_num = (const int*)d_in[3];
    const float* W_vis   = (const float*)d_in[4];
    const float* b_vis   = (const float*)d_in[5];
    const float* W_txt   = (const float*)d_in[6];
    const float* b_txt   = (const float*)d_in[7];
    const float* W_patch = (const float*)d_in[8];
    const float* b_patch = (const float*)d_in[9];
    const float* W_att   = (const float*)d_in[10];
    const float* b_att   = (const float*)d_in[11];
    float* out = (float*)d_out;

    dim3 blk(256);

    // 1: weight transposes
    wt_kernel<<<dim3(24, 8, 4), blk>>>(W_patch, W_att, W_vis, W_txt);
    // 2: merged projections (+ patchT/attT transposed outputs)
    const int proj_smem = 3 * (PA_SZ + PB_SZ) * 4;
    cudaFuncSetAttribute(proj2_kernel, cudaFuncAttributeMaxDynamicSharedMemorySize,
                         proj_smem);
    proj2_kernel<<<dim3(4, 113), blk, proj_smem>>>(vf, tf, b_patch, b_att,
                                                   b_vis, b_txt, out);
    // 3: fused M GEMM + norms/gram/means
    const int mg_smem = 2 * MBUF * 4;
    cudaFuncSetAttribute(mgemm_prep_kernel, cudaFuncAttributeMaxDynamicSharedMemorySize,
                         mg_smem);
    mgemm_prep_kernel<<<1272, blk, mg_smem>>>(att_num, out);
    // 4: pair kernel — 384 threads, duplicated-weight stage C
    const int smem_bytes = SMEM_F * 4;
    cudaFuncSetAttribute(pair_kernel, cudaFuncAttributeMaxDynamicSharedMemorySize,
                         smem_bytes);
    pair_kernel<<<dim3(NB, NB), dim3(384), smem_bytes>>>(mask, att_num, out + SIM_OFF);
}

// round 16
// speedup vs baseline: 1.0879x; 1.0879x over previous
#include <cuda_runtime.h>
#include <cstdint>
#include <math.h>

// Problem constants
#define NB 32     // batch
#define NP 192    // patches
#define NA 30     // attributes
#define NE 256    // embed dim
#define NK 768    // input feature dim
#define SV 193    // visual seq len
#define ST 31     // textual seq len

#define VE_OFF 0
#define TE_OFF 8192
#define PM_OFF 16384
#define AM_OFF 24576
#define SIM_OFF 32768

// Scratch
__device__ float g_patch[NB * NP * NE];    // [v][p][e]
__device__ float g_patchT[NB * NE * NP];   // [v][e][p]
__device__ float g_att[NB * NA * NE];      // [t][a][e]
__device__ float g_attT[NE * NB * NA];     // [e][row]
__device__ float g_rp[NB * NP];
__device__ float g_ra[NB * NA];
__device__ float g_G[NB * NA * 32];
__device__ float g_WT[4 * NK * NE];        // transposed weights [seg][k][n]
__device__ float g_M[NB * NB * NA * NP];   // [v][t*30+a][p]

typedef unsigned long long ull;

__device__ __forceinline__ void fma2(ull& d, ull a, ull b) {
    asm("fma.rn.f32x2 %0, %1, %2, %3;" : "=l"(d) : "l"(a), "l"(b), "l"(d));
}
__device__ __forceinline__ ull pk2(float x, float y) {
    ull r; asm("mov.b64 %0, {%1,%2};" : "=l"(r) : "f"(x), "f"(y)); return r;
}
__device__ __forceinline__ float2 upk(ull v) {
    float2 r; asm("mov.b64 {%0,%1}, %2;" : "=f"(r.x), "=f"(r.y) : "l"(v)); return r;
}
__device__ __forceinline__ void cpa16(uint32_t s, const void* g) {
    asm volatile("cp.async.cg.shared.global [%0], [%1], 16;\n" :: "r"(s), "l"(g));
}
__device__ __forceinline__ void cpa_commit() {
    asm volatile("cp.async.commit_group;\n" ::: "memory");
}
template<int N>
__device__ __forceinline__ void cpa_wait() {
    asm volatile("cp.async.wait_group %0;\n" :: "n"(N) : "memory");
}

// ---------------------------------------------------------------------------
// Transpose the four weight matrices [256][768] -> g_WT[seg][768][256]
// ---------------------------------------------------------------------------
__global__ __launch_bounds__(256) void wt_kernel(
    const float* __restrict__ W0, const float* __restrict__ W1,
    const float* __restrict__ W2, const float* __restrict__ W3)
{
    __shared__ float ts[32][33];
    const int z = blockIdx.z;
    const float* W = (z == 0) ? W0 : (z == 1) ? W1 : (z == 2) ? W2 : W3;
    const int k0 = blockIdx.x * 32;
    const int n0 = blockIdx.y * 32;
    const int lane = threadIdx.x & 31, wid = threadIdx.x >> 5;
#pragma unroll
    for (int i = 0; i < 4; i++)
        ts[wid + 8 * i][lane] = W[(size_t)(n0 + wid + 8 * i) * NK + k0 + lane];
    __syncthreads();
    float* WT = g_WT + (size_t)z * NK * NE;
#pragma unroll
    for (int i = 0; i < 4; i++)
        WT[(size_t)(k0 + wid + 8 * i) * NE + n0 + lane] = ts[lane][wid + 8 * i];
}

// ---------------------------------------------------------------------------
// Merged projection GEMM, cp.async triple-buffered.
// seg 0 (patch) additionally writes g_patchT; seg 1 (att) writes g_attT.
// ---------------------------------------------------------------------------
#define PA_SZ (64 * 36)
#define PB_SZ (32 * 64)
__global__ __launch_bounds__(256) void proj2_kernel(
    const float* __restrict__ vf, const float* __restrict__ tf,
    const float* __restrict__ b_patch, const float* __restrict__ b_att,
    const float* __restrict__ b_vis, const float* __restrict__ b_txt,
    float* __restrict__ out)
{
    extern __shared__ float psm[];

    const int y = blockIdx.y;
    int seg, my;
    if (y < 96)       { seg = 0; my = y; }
    else if (y < 111) { seg = 1; my = y - 96; }
    else if (y == 111){ seg = 2; my = 0; }
    else              { seg = 3; my = 0; }

    const int M  = (seg == 0) ? NB * NP : (seg == 1) ? NB * NA : NB;
    const int S  = (seg == 0 || seg == 2) ? SV : ST;
    const int gs = (seg == 0) ? NP : (seg == 1) ? NA : 1;
    const int off= (seg <= 1) ? 1 : 0;
    const float* X = (seg == 0 || seg == 2) ? vf : tf;
    const float* bias = (seg == 0) ? b_patch : (seg == 1) ? b_att
                       : (seg == 2) ? b_vis : b_txt;
    float* obase;
    if (seg == 0) obase = g_patch;
    else if (seg == 1) obase = g_att;
    else if (seg == 2) obase = out + VE_OFF;
    else obase = out + TE_OFF;
    const float* WT = g_WT + (size_t)seg * NK * NE;

    const int col0 = blockIdx.x * 64;
    const int row0 = my * 64;
    const int tid = threadIdx.x;
    const int tm = tid >> 4, tn = tid & 15;

    const int c1 = tid + 256;
    const int ar0 = tid >> 3,  ac0 = (tid & 7) << 2;
    const int ar1 = c1 >> 3,   ac1 = (c1 & 7) << 2;
    int gr0 = row0 + ar0; if (gr0 >= M) gr0 = M - 1;
    int gr1 = row0 + ar1; if (gr1 >= M) gr1 = M - 1;
    const float* aS0 = X + (size_t)((gr0 / gs) * S + off + gr0 % gs) * NK + ac0;
    const float* aS1 = X + (size_t)((gr1 / gs) * S + off + gr1 % gs) * NK + ac1;
    const uint32_t aD0 = (ar0 * 36 + ac0) * 4;
    const uint32_t aD1 = (ar1 * 36 + ac1) * 4;
    const int bk0 = tid >> 4, bc0 = (tid & 15) << 2;
    const int bk1 = c1 >> 4,  bc1 = (c1 & 15) << 2;
    const float* bS0 = WT + (size_t)bk0 * NE + col0 + bc0;
    const float* bS1 = WT + (size_t)bk1 * NE + col0 + bc1;
    const uint32_t bD0 = (bk0 * 64 + bc0) * 4;
    const uint32_t bD1 = (bk1 * 64 + bc1) * 4;

    const uint32_t sA = (uint32_t)__cvta_generic_to_shared(psm);
    const uint32_t sB = (uint32_t)__cvta_generic_to_shared(psm + 3 * PA_SZ);

    ull c2[4][2];
#pragma unroll
    for (int i = 0; i < 4; i++) { c2[i][0] = 0ull; c2[i][1] = 0ull; }

#pragma unroll
    for (int pb = 0; pb < 2; pb++) {
        const uint32_t oA = sA + pb * (PA_SZ * 4);
        const uint32_t oB = sB + pb * (PB_SZ * 4);
        const int k0 = pb * 32;
        cpa16(oA + aD0, aS0 + k0);
        cpa16(oA + aD1, aS1 + k0);
        cpa16(oB + bD0, bS0 + (size_t)k0 * NE);
        cpa16(oB + bD1, bS1 + (size_t)k0 * NE);
        cpa_commit();
    }

    for (int it = 0; it < 24; it++) {
        if (it < 22) {
            const int nb = (it + 2) % 3;
            const uint32_t oA = sA + nb * (PA_SZ * 4);
            const uint32_t oB = sB + nb * (PB_SZ * 4);
            const int k0 = (it + 2) * 32;
            cpa16(oA + aD0, aS0 + k0);
            cpa16(oA + aD1, aS1 + k0);
            cpa16(oB + bD0, bS0 + (size_t)k0 * NE);
            cpa16(oB + bD1, bS1 + (size_t)k0 * NE);
            cpa_commit();
            cpa_wait<2>();
        } else if (it == 22) {
            cpa_wait<1>();
        } else {
            cpa_wait<0>();
        }
        __syncthreads();

        const float* A = psm + (it % 3) * PA_SZ;
        const float* B = psm + 3 * PA_SZ + (it % 3) * PB_SZ;
#pragma unroll
        for (int q = 0; q < 8; q++) {
            float4 a[4];
#pragma unroll
            for (int i = 0; i < 4; i++)
                a[i] = *(const float4*)&A[(tm * 4 + i) * 36 + q * 4];
#pragma unroll
            for (int j = 0; j < 4; j++) {
                ulonglong2 bb = *(const ulonglong2*)&B[(q * 4 + j) * 64 + tn * 4];
#pragma unroll
                for (int i = 0; i < 4; i++) {
                    float av = (j == 0) ? a[i].x : (j == 1) ? a[i].y
                             : (j == 2) ? a[i].z : a[i].w;
                    ull d = pk2(av, av);
                    fma2(c2[i][0], d, bb.x);
                    fma2(c2[i][1], d, bb.y);
                }
            }
        }
        __syncthreads();
    }

    const float4 b4 = *(const float4*)&bias[col0 + tn * 4];
    float* Cs = psm;   // 64 x 69 staging (buffers dead)
#pragma unroll
    for (int i = 0; i < 4; i++) {
        int r = row0 + tm * 4 + i;
        float2 lo = upk(c2[i][0]), hi = upk(c2[i][1]);
        float4 o;
        o.x = lo.x + b4.x; o.y = lo.y + b4.y;
        o.z = hi.x + b4.z; o.w = hi.y + b4.w;
        if (r < M)
            *(float4*)&obase[(size_t)r * NE + col0 + tn * 4] = o;
        if (seg <= 1) {
            float* cr = &Cs[(tm * 4 + i) * 69 + tn * 4];
            cr[0] = o.x; cr[1] = o.y; cr[2] = o.z; cr[3] = o.w;
        }
    }

    if (seg == 0) {
        __syncthreads();
        const int v = row0 / NP, p0 = row0 % NP;
        float* dT = g_patchT + (size_t)v * NE * NP;
#pragma unroll
        for (int i = 0; i < 16; i++) {
            int idx = tid + 256 * i;
            int e = idx >> 6, p = idx & 63;
            dT[(size_t)(col0 + e) * NP + p0 + p] = Cs[p * 69 + e];
        }
    } else if (seg == 1) {
        __syncthreads();
#pragma unroll
        for (int i = 0; i < 16; i++) {
            int idx = tid + 256 * i;
            int e = idx >> 6, p = idx & 63;
            g_attT[(size_t)(col0 + e) * (NB * NA) + row0 + p] = Cs[p * 69 + e];
        }
    }
}

// ---------------------------------------------------------------------------
// Fused M GEMM + prep (unchanged).
// ---------------------------------------------------------------------------
#define MA_SZ (32 * 196)
#define MB_SZ (32 * 100)
#define MBUF  (MA_SZ + MB_SZ)
__global__ __launch_bounds__(256, 2) void mgemm_prep_kernel(
    const int* __restrict__ att_nums, float* __restrict__ out)
{
    extern __shared__ float psm[];
    const int r = blockIdx.x;
    const int tid = threadIdx.x;
    const int lane = tid & 31, wid = tid >> 5;

    if (r < 320) {
        const int nt = r & 1;
        const int mt = (r >> 1) % 5;
        const int v  = r / 10;
        const float* Bg = g_patchT + (size_t)v * NE * NP;
        float* C = g_M + (size_t)v * (NB * NA) * NP;

        const int tm = tid >> 4, tn = tid & 15;
        const uint32_t sbase = (uint32_t)__cvta_generic_to_shared(psm);

        ull c2[12][3];
#pragma unroll
        for (int i = 0; i < 12; i++)
#pragma unroll
            for (int j = 0; j < 3; j++) c2[i][j] = 0ull;

        int crow[9], coff[9];
        bool isA[9];
#pragma unroll
        for (int j = 0; j < 9; j++) {
            int c = tid + 256 * j;
            if (c < 1536) { isA[j] = true;  crow[j] = c / 48; coff[j] = (c % 48) * 4; }
            else { int b = c - 1536; isA[j] = false; crow[j] = b / 24; coff[j] = (b % 24) * 4; }
        }

#pragma unroll
        for (int j = 0; j < 9; j++) {
            if (isA[j])
                cpa16(sbase + (uint32_t)(crow[j] * 196 + coff[j]) * 4,
                      g_attT + (size_t)crow[j] * (NB * NA) + mt * 192 + coff[j]);
            else
                cpa16(sbase + (uint32_t)(MA_SZ + crow[j] * 100 + coff[j]) * 4,
                      Bg + (size_t)crow[j] * NP + nt * 96 + coff[j]);
        }
        cpa_commit();

        for (int it = 0; it < 8; it++) {
            if (it < 7) {
                const int nb = (it + 1) & 1;
                const int k0 = (it + 1) * 32;
                const uint32_t bb = sbase + (uint32_t)(nb * MBUF) * 4;
#pragma unroll
                for (int j = 0; j < 9; j++) {
                    if (isA[j])
                        cpa16(bb + (uint32_t)(crow[j] * 196 + coff[j]) * 4,
                              g_attT + (size_t)(k0 + crow[j]) * (NB * NA) + mt * 192 + coff[j]);
                    else
                        cpa16(bb + (uint32_t)(MA_SZ + crow[j] * 100 + coff[j]) * 4,
                              Bg + (size_t)(k0 + crow[j]) * NP + nt * 96 + coff[j]);
                }
                cpa_commit();
                cpa_wait<1>();
            } else {
                cpa_wait<0>();
            }
            __syncthreads();

            const float* As = psm + (it & 1) * MBUF;
            const float* Bs = As + MA_SZ;
#pragma unroll
            for (int k = 0; k < 32; k++) {
                const float* ap = &As[k * 196 + tm * 12];
                float4 a0 = *(const float4*)&ap[0];
                float4 a1 = *(const float4*)&ap[4];
                float4 a2 = *(const float4*)&ap[8];
                const float* bp = &Bs[k * 100 + tn * 6];
                ull b0 = *(const ull*)&bp[0];
                ull b1 = *(const ull*)&bp[2];
                ull b2 = *(const ull*)&bp[4];
                float av[12] = {a0.x, a0.y, a0.z, a0.w, a1.x, a1.y, a1.z, a1.w,
                                a2.x, a2.y, a2.z, a2.w};
#pragma unroll
                for (int i = 0; i < 12; i++) {
                    ull d = pk2(av[i], av[i]);
                    fma2(c2[i][0], d, b0);
                    fma2(c2[i][1], d, b1);
                    fma2(c2[i][2], d, b2);
                }
            }
            __syncthreads();
        }

#pragma unroll
        for (int i = 0; i < 12; i++) {
            float* cr = &C[(size_t)(mt * 192 + tm * 12 + i) * NP + nt * 96 + tn * 6];
#pragma unroll
            for (int j = 0; j < 3; j++) {
                float2 f = upk(c2[i][j]);
                *(float2*)&cr[2 * j] = f;
            }
        }
    } else if (r < 1208) {
        const int w = (r - 320) * 8 + wid;
        if (w >= NB * NP + NB * NA) return;
        const float* row;
        float* dst;
        if (w < NB * NP) { row = g_patch + (size_t)w * NE; dst = &g_rp[w]; }
        else { row = g_att + (size_t)(w - NB * NP) * NE; dst = &g_ra[w - NB * NP]; }
        float4 x0 = *(const float4*)&row[lane * 4];
        float4 x1 = *(const float4*)&row[128 + lane * 4];
        float ss = x0.x * x0.x + x0.y * x0.y + x0.z * x0.z + x0.w * x0.w
                 + x1.x * x1.x + x1.y * x1.y + x1.z * x1.z + x1.w * x1.w;
#pragma unroll
        for (int o = 16; o > 0; o >>= 1) ss += __shfl_xor_sync(~0u, ss, o);
        if (lane == 0) *dst = rsqrtf(fmaxf(ss, 1e-24f));
    } else if (r < 1240) {
        const int t = r - 1208;
        const float* ap = g_att + (size_t)t * NA * NE;
        for (int i = tid; i < NA * NE; i += 256) psm[i] = ap[i];
        __syncthreads();
        for (int idx = tid; idx < NA * NA; idx += 256) {
            int a = idx / NA, b = idx % NA;
            const float* ra = psm + a * NE;
            const float* rb = psm + b * NE;
            float acc = 0.f;
#pragma unroll 4
            for (int e = 0; e < NE; e += 4) {
                float4 x = *(float4*)&ra[e];
                float4 y = *(float4*)&rb[e];
                acc += x.x * y.x + x.y * y.y + x.z * y.z + x.w * y.w;
            }
            g_G[t * NA * 32 + a * 32 + b] = acc;
        }
    } else {
        const int b = r - 1240;
        const int e = tid;
        float pm = 0.f;
        const float* pb = g_patch + (size_t)b * NP * NE + e;
#pragma unroll 4
        for (int p = 0; p < NP; p++) pm += pb[(size_t)p * NE];
        out[PM_OFF + b * NE + e] = pm / (float)NP;
        float am = 0.f;
        const float* ab = g_att + (size_t)b * NA * NE + e;
#pragma unroll
        for (int a = 0; a < NA; a++) am += ab[(size_t)a * NE];
        out[AM_OFF + b * NE + e] = am / (float)att_nums[b];
    }
}

// ---------------------------------------------------------------------------
// Pair kernel smem layout (floats). Total 27009 fl = 108036 B -> 2 CTAs/SM.
// Stage C reads patch DIRECTLY from global (no smem staging, no barriers).
// ---------------------------------------------------------------------------
#define SB_M    0          /* 5760  : M [30][192] */
#define SB_A1D  5760       /* 11520 : attn1 dup [30][384] */
#define SB_RG   17280      /* 8192  : A2 (5760) / comb (7680) */
#define SB_G    25472      /* 960 */
#define SB_RA   26432      /* 32 */
#define SB_RP   26464      /* 192 */
#define SB_PADF 26656      /* 32 */
#define SB_W    26688      /* 192 */
#define SB_W2   26880      /* 32 */
#define SB_C    26912      /* 32 */
#define SB_RED  26944      /* 64 */
#define SB_AN   27008      /* 1 */
#define SMEM_F  27009

__global__ __launch_bounds__(384, 2) void pair_kernel(const int* __restrict__ mask,
                                                      const int* __restrict__ att_nums,
                                                      float* __restrict__ out_sim)
{
    extern __shared__ float sm[];
    const int v = blockIdx.x, t = blockIdx.y;
    const int tid = threadIdx.x, lane = tid & 31, wid = tid >> 5;

    float* s_M    = sm + SB_M;
    float* s_A1d  = sm + SB_A1D;
    float* s_rg   = sm + SB_RG;
    float* s_A2   = sm + SB_RG;      // alias phase 1
    float* s_G    = sm + SB_G;
    float* s_ra   = sm + SB_RA;
    float* s_rp   = sm + SB_RP;
    float* s_padf = sm + SB_PADF;
    float* s_w    = sm + SB_W;
    float* s_w2   = sm + SB_W2;
    float* s_c    = sm + SB_C;
    float* s_red  = sm + SB_RED;
    float* s_an   = sm + SB_AN;

    // ---- preload (vectorized) ----
    const float* Mg = g_M + ((size_t)v * (NB * NA) + t * NA) * NP;
    for (int i = tid; i < NA * NP / 4; i += 384)
        *(float4*)&s_M[i * 4] = *(const float4*)&Mg[i * 4];
    const float* gGp = g_G + t * NA * 32;
    for (int i = tid; i < NA * 8; i += 384)
        *(float4*)&s_G[i * 4] = *(const float4*)&gGp[i * 4];
    if (tid < NA) {
        s_ra[tid] = g_ra[t * NA + tid];
        s_padf[tid] = (mask[t * NA + tid] != 0) ? 1.f : 0.f;
    }
    if (tid < NP) s_rp[tid] = g_rp[v * NP + tid];
    if (tid == 0) s_an[0] = (float)att_nums[t];
    __syncthreads();

    const float* pbase = g_patch + (size_t)v * NP * NE;

    // ---- attn1: softmax over p, written duplicated (warp per row) ----
    for (int r = wid; r < NA; r += 12) {
        const float ra = s_ra[r];
        float x[6];
        float mx = 0.f;
#pragma unroll
        for (int j = 0; j < 6; j++) {
            int p = lane + j * 32;
            float d = fmaxf(s_M[r * NP + p] * ra * s_rp[p], 0.f) * 20.f;
            x[j] = d; mx = fmaxf(mx, d);
        }
#pragma unroll
        for (int o = 16; o > 0; o >>= 1) mx = fmaxf(mx, __shfl_xor_sync(~0u, mx, o));
        float ssum = 0.f;
#pragma unroll
        for (int j = 0; j < 6; j++) { x[j] = __expf(x[j] - mx); ssum += x[j]; }
#pragma unroll
        for (int o = 16; o > 0; o >>= 1) ssum += __shfl_xor_sync(~0u, ssum, o);
        const float rinv = 1.f / ssum;
#pragma unroll
        for (int j = 0; j < 6; j++) {
            float val = x[j] * rinv;
            int p = lane + j * 32;
            float2 d2; d2.x = val; d2.y = val;
            *(float2*)&s_A1d[r * 384 + 2 * p] = d2;
        }
    }

    // ---- attn2: 2 threads per p (lane-adjacent), 15 a's each.
    //      masked softmax + f32x2 Gram quadratic -> w_p; A2 stored ----
    {
        const int p = tid >> 1;
        const int sub = tid & 1;
        const int abase = sub * 15;
        const float rp = s_rp[p];
        float vv[15];
        float mx = -1.f;
#pragma unroll
        for (int j = 0; j < 15; j++) {
            const int a = abase + j;
            float d = fmaxf(s_M[a * NP + p] * s_ra[a] * rp, 0.f) * 20.f;
            if (s_padf[a] == 0.f) { vv[j] = d; mx = fmaxf(mx, d); }
            else                  { vv[j] = -1.f; }
        }
        mx = fmaxf(mx, __shfl_xor_sync(~0u, mx, 1));
        float ssum = 0.f;
#pragma unroll
        for (int j = 0; j < 15; j++) {
            float e = (vv[j] < 0.f) ? 0.f : __expf(vv[j] - mx);
            vv[j] = e; ssum += e;
        }
        ssum += __shfl_xor_sync(~0u, ssum, 1);
        const float rinv = 1.f / ssum;
#pragma unroll
        for (int j = 0; j < 15; j++) { vv[j] *= rinv; s_A2[(abase + j) * NP + p] = vv[j]; }
        float ov[15];
#pragma unroll
        for (int j = 0; j < 15; j++) ov[j] = __shfl_xor_sync(~0u, vv[j], 1);
        const int pb0 = sub ? 16 : 0;
        const int sb  = sub ? 15 : 14;
        ull y2[7];
#pragma unroll
        for (int k = 0; k < 7; k++) y2[k] = 0ull;
        float ysc = 0.f;
#pragma unroll
        for (int a = 0; a < NA; a++) {
            float va = (a < 15) ? (sub ? ov[a] : vv[a])
                                : (sub ? vv[a - 15] : ov[a - 15]);
            ull vd = pk2(va, va);
            const float* Gr = s_G + a * 32;
#pragma unroll
            for (int k = 0; k < 7; k++)
                fma2(y2[k], vd, *(const ull*)&Gr[pb0 + 2 * k]);
            ysc = fmaf(va, Gr[sb], ysc);
        }
        float z = 0.f;
        const int vj0 = sub ? 1 : 0;
#pragma unroll
        for (int k = 0; k < 7; k++) {
            float2 yk = upk(y2[k]);
            z = fmaf(vv[vj0 + 2 * k], yk.x, z);
            z = fmaf(vv[vj0 + 2 * k + 1], yk.y, z);
        }
        z = fmaf(vv[sub ? 0 : 14], ysc, z);
        z += __shfl_xor_sync(~0u, z, 1);
        if (sub == 0) s_w[p] = rsqrtf(fmaxf(z, 1e-24f));
    }
    __syncthreads();

    // ---- c_a = sum_p attn2[a][p] * w_p (warp per row) ----
    for (int r = wid; r < NA; r += 12) {
        float cc = 0.f;
#pragma unroll
        for (int j = 0; j < 6; j++) {
            int p = lane + j * 32;
            cc = fmaf(s_A2[r * NP + p], s_w[p], cc);
        }
#pragma unroll
        for (int o = 16; o > 0; o >>= 1) cc += __shfl_xor_sync(~0u, cc, o);
        if (lane == 0) s_c[r] = cc;
    }
    __syncthreads();   // c done; s_rg free for comb

    // ---- Stage C: ||attend_patch_a||^2, patch read DIRECTLY from global.
    // 384 threads: h = p-half (contiguous 96 p's), 6 a-groups x 5 a's,
    // 32 e-threads. Weights via LDS.64 (w,w) broadcasts from s_A1d.
    {
        const int h  = (tid >= 192) ? 1 : 0;
        const int g  = tid - h * 192;     // 0..191
        const int a0 = (g >> 5) * 5;      // 0,5,...,25
        const int e4 = (g & 31) * 4;
        const float* pb0 = pbase + (size_t)(h * 96) * NE;

        ull acc[5][4];
#pragma unroll
        for (int a = 0; a < 5; a++)
#pragma unroll
            for (int k = 0; k < 4; k++) acc[a][k] = 0ull;

#pragma unroll 1
        for (int pp = 0; pp < 96; pp += 4) {
            // 8 independent LDG.128 -> MLP 8
            ulonglong2 lo0 = *(const ulonglong2*)&pb0[(size_t)(pp + 0) * NE + e4];
            ulonglong2 hi0 = *(const ulonglong2*)&pb0[(size_t)(pp + 0) * NE + 128 + e4];
            ulonglong2 lo1 = *(const ulonglong2*)&pb0[(size_t)(pp + 1) * NE + e4];
            ulonglong2 hi1 = *(const ulonglong2*)&pb0[(size_t)(pp + 1) * NE + 128 + e4];
            ulonglong2 lo2 = *(const ulonglong2*)&pb0[(size_t)(pp + 2) * NE + e4];
            ulonglong2 hi2 = *(const ulonglong2*)&pb0[(size_t)(pp + 2) * NE + 128 + e4];
            ulonglong2 lo3 = *(const ulonglong2*)&pb0[(size_t)(pp + 3) * NE + e4];
            ulonglong2 hi3 = *(const ulonglong2*)&pb0[(size_t)(pp + 3) * NE + 128 + e4];
            const int pg = h * 96 + pp;
#pragma unroll
            for (int a = 0; a < 5; a++) {
                const float* dup = &s_A1d[(a0 + a) * 384 + 2 * pg];
                ull w0 = *(const ull*)&dup[0];
                ull w1 = *(const ull*)&dup[2];
                ull w2 = *(const ull*)&dup[4];
                ull w3 = *(const ull*)&dup[6];
                fma2(acc[a][0], w0, lo0.x); fma2(acc[a][1], w0, lo0.y);
                fma2(acc[a][2], w0, hi0.x); fma2(acc[a][3], w0, hi0.y);
                fma2(acc[a][0], w1, lo1.x); fma2(acc[a][1], w1, lo1.y);
                fma2(acc[a][2], w1, hi1.x); fma2(acc[a][3], w1, hi1.y);
                fma2(acc[a][0], w2, lo2.x); fma2(acc[a][1], w2, lo2.y);
                fma2(acc[a][2], w2, hi2.x); fma2(acc[a][3], w2, hi2.y);
                fma2(acc[a][0], w3, lo3.x); fma2(acc[a][1], w3, lo3.y);
                fma2(acc[a][2], w3, hi3.x); fma2(acc[a][3], w3, hi3.y);
            }
        }

        // combine halves (vector add BEFORE squaring): one pass, 5 a's
        float* s_comb = s_rg;    // 192 * 40 = 7680 <= 8192
        __syncthreads();         // ensure c_a/A2 phase fully drained before reuse
        if (h == 1) {
#pragma unroll
            for (int a = 0; a < 5; a++)
#pragma unroll
                for (int k = 0; k < 4; k++) {
                    float2 f = upk(acc[a][k]);
                    *(float2*)&s_comb[g * 40 + a * 8 + k * 2] = f;
                }
        }
        __syncthreads();
        if (h == 0) {
#pragma unroll
            for (int a = 0; a < 5; a++) {
                float ss = 0.f;
#pragma unroll
                for (int k = 0; k < 4; k++) {
                    float2 fc = *(const float2*)&s_comb[g * 40 + a * 8 + k * 2];
                    float2 f = upk(acc[a][k]);
                    float sx = f.x + fc.x, sy = f.y + fc.y;
                    ss += sx * sx + sy * sy;
                }
#pragma unroll
                for (int o = 16; o > 0; o >>= 1)
                    ss += __shfl_xor_sync(~0u, ss, o);
                if (lane == 0) s_red[a0 + a] = ss;
            }
        }
        __syncthreads();
    }
    if (tid < NA)
        s_w2[tid] = (s_padf[tid] != 0.f) ? 0.f : rsqrtf(fmaxf(s_red[tid], 1e-24f));
    __syncthreads();

    // ---- final: sim = sum_p d_p * (sum_a c_a M[a][p]) / (an*30) ----
    float fp = 0.f;
    if (tid < NP) {
        const int p = tid;
        float dp = 0.f, mp = 0.f;
#pragma unroll
        for (int a = 0; a < NA; a++) {
            dp = fmaf(s_A1d[a * 384 + 2 * p], s_w2[a], dp);
            mp = fmaf(s_c[a], s_M[a * NP + p], mp);
        }
        fp = dp * mp;
    }
#pragma unroll
    for (int o = 16; o > 0; o >>= 1) fp += __shfl_xor_sync(~0u, fp, o);
    if (lane == 0) s_red[32 + wid] = fp;
    __syncthreads();
    if (tid == 0) {
        float tot = 0.f;
#pragma unroll
        for (int w2i = 0; w2i < 12; w2i++) tot += s_red[32 + w2i];
        out_sim[t * NB + v] = tot / (s_an[0] * (float)NA);
    }
}

// ---------------------------------------------------------------------------
extern "C" void kernel_launch(void* const* d_in, const int* in_sizes, int n_in,
                              void* d_out, int out_size)
{
    const float* vf      = (const float*)d_in[0];
    const float* tf      = (const float*)d_in[1];
    const int*   mask    = (const int*)d_in[2];
    const int*   att_num = (const int*)d_in[3];
    const float* W_vis   = (const float*)d_in[4];
    const float* b_vis   = (const float*)d_in[5];
    const float* W_txt   = (const float*)d_in[6];
    const float* b_txt   = (const float*)d_in[7];
    const float* W_patch = (const float*)d_in[8];
    const float* b_patch = (const float*)d_in[9];
    const float* W_att   = (const float*)d_in[10];
    const float* b_att   = (const float*)d_in[11];
    float* out = (float*)d_out;

    dim3 blk(256);

    // 1: weight transposes
    wt_kernel<<<dim3(24, 8, 4), blk>>>(W_patch, W_att, W_vis, W_txt);
    // 2: merged projections (+ patchT/attT transposed outputs)
    const int proj_smem = 3 * (PA_SZ + PB_SZ) * 4;
    cudaFuncSetAttribute(proj2_kernel, cudaFuncAttributeMaxDynamicSharedMemorySize,
                         proj_smem);
    proj2_kernel<<<dim3(4, 113), blk, proj_smem>>>(vf, tf, b_patch, b_att,
                                                   b_vis, b_txt, out);
    // 3: fused M GEMM + norms/gram/means
    const int mg_smem = 2 * MBUF * 4;
    cudaFuncSetAttribute(mgemm_prep_kernel, cudaFuncAttributeMaxDynamicSharedMemorySize,
                         mg_smem);
    mgemm_prep_kernel<<<1272, blk, mg_smem>>>(att_num, out);
    // 4: pair kernel — direct-LDG stage C (no staging, no stage-C barriers)
    const int smem_bytes = SMEM_F * 4;
    cudaFuncSetAttribute(pair_kernel, cudaFuncAttributeMaxDynamicSharedMemorySize,
                         smem_bytes);
    pair_kernel<<<dim3(NB, NB), dim3(384), smem_bytes>>>(mask, att_num, out + SIM_OFF);
}